// round 8
// baseline (speedup 1.0000x reference)
#include <cuda_runtime.h>
#include <cuda_fp16.h>
#include <cstdint>

// ============================================================
// AWQLinear via fp16 mma.sync m16n8k16 (same mantissa as tf32).
// y = (x/alpha) @ W_hat^T + bias, M=4096 N=11008 K=4096.
// R7: 128x128 CTA (4 warps of 64x64), 2 CTAs/SM to cover the
// per-iter sync seam; 3-stage cp.async pipeline; merged prep.
// ============================================================

#define IN_F   4096
#define OUT_F  11008
#define MROWS  4096
#define NKT    64            // K / 64
#define TM     128
#define TN     128
#define A_KT_BYTES 16384     // 128 rows x 64 k x 2B
#define B_KT_BYTES 16384
#define STAGE_BYTES (A_KT_BYTES + B_KT_BYTES)   // 32KB
#define SMEM_BYTES (3 * STAGE_BYTES)            // 96KB (2 CTAs/SM)

// chunks: 16B units, fragment-major
#define XCHUNKS (MROWS * IN_F / 8)              // 2,097,152
#define WCHUNKS (OUT_F * IN_F / 8)              // 5,636,096
#define WBLOCKS (WCHUNKS / 256)                 // 22016
#define XBLOCKS (XCHUNKS / 256)                 // 8192

__device__ __half2 g_A[(size_t)XCHUNKS * 4];    // 32MB
__device__ __half2 g_B[(size_t)WCHUNKS * 4];    // 90MB

// ---------------- helpers ----------------
__device__ __forceinline__ uint32_t smem_u32(const void* p) {
    uint32_t a;
    asm("{ .reg .u64 t; cvta.to.shared.u64 t, %1; cvt.u32.u64 %0, t; }"
        : "=r"(a) : "l"(p));
    return a;
}
__device__ __forceinline__ void cp16(uint32_t dst, const void* src) {
    asm volatile("cp.async.cg.shared.global [%0], [%1], 16;"
                 :: "r"(dst), "l"(src) : "memory");
}
#define CP_COMMIT() asm volatile("cp.async.commit_group;" ::: "memory")
#define CP_WAIT0()  asm volatile("cp.async.wait_group 0;" ::: "memory")

__device__ __forceinline__ void mma_f16(float4& d, const uint4 a,
                                        const uint32_t b0, const uint32_t b1) {
    asm("mma.sync.aligned.m16n8k16.row.col.f32.f16.f16.f32 "
        "{%0,%1,%2,%3}, {%4,%5,%6,%7}, {%8,%9}, {%0,%1,%2,%3};"
        : "+f"(d.x), "+f"(d.y), "+f"(d.z), "+f"(d.w)
        : "r"(a.x), "r"(a.y), "r"(a.z), "r"(a.w), "r"(b0), "r"(b1));
}
__device__ __forceinline__ uint32_t h2u(__half2 h) { return *(uint32_t*)&h; }

// ---------------- merged prep: 1 thread = one 16B fragment chunk --------
// W chunk (nb,kt,c): c=((s*8+jp)*32+th); rows o0=(nb*128)+(jp*16)+(th>>2),
//   o0+8; k0=(kt*64)+(s*16)+((th&3)*2), k0+8.
// X chunk (mb,kt,c): c=((s*8+it)*32+th); rows mb*128+it*16+(th>>2), +8;
//   k same as W.
__global__ void prep_all_kernel(const float* __restrict__ x,
                                const float* __restrict__ alpha,
                                const int* __restrict__ q,
                                const float* __restrict__ sc) {
    int bid = blockIdx.x;
    if (bid < WBLOCKS) {
        int j = bid * 256 + threadIdx.x;
        int blk = j >> 10, c = j & 1023;
        int th = c & 31, jp = (c >> 5) & 7, s = c >> 8;
        int nb = blk >> 6, kt = blk & 63;
        int o0 = (nb << 7) + (jp << 4) + (th >> 2);
        int k0 = (kt << 6) + (s << 4) + ((th & 3) << 1);
        int sblk = (kt << 1) + (s >> 1);
        const int* q0 = q + ((size_t)o0 << 12) + k0;
        const int* q8 = q0 + (8 << 12);
        float s0 = sc[(o0 << 7) + sblk];
        float s1 = sc[((o0 + 8) << 7) + sblk];
        int2 a0 = *(const int2*)(q0);
        int2 a2 = *(const int2*)(q0 + 8);
        int2 b0 = *(const int2*)(q8);
        int2 b2 = *(const int2*)(q8 + 8);
        uint4 o;
        o.x = h2u(__floats2half2_rn((float)(a0.x - 8) * s0, (float)(a0.y - 8) * s0));
        o.y = h2u(__floats2half2_rn((float)(a2.x - 8) * s0, (float)(a2.y - 8) * s0));
        o.z = h2u(__floats2half2_rn((float)(b0.x - 8) * s1, (float)(b0.y - 8) * s1));
        o.w = h2u(__floats2half2_rn((float)(b2.x - 8) * s1, (float)(b2.y - 8) * s1));
        *(uint4*)(g_B + (size_t)j * 4) = o;
    } else {
        int j = (bid - WBLOCKS) * 256 + threadIdx.x;
        int blk = j >> 10, c = j & 1023;
        int th = c & 31, it = (c >> 5) & 7, s = c >> 8;
        int mb = blk >> 6, kt = blk & 63;
        int row0 = (mb << 7) + (it << 4) + (th >> 2);
        int k0 = (kt << 6) + (s << 4) + ((th & 3) << 1);
        const float* x0 = x + ((size_t)row0 << 12) + k0;
        const float* x8 = x0 + (8 << 12);
        float ia0 = 1.0f / alpha[k0],     ia1 = 1.0f / alpha[k0 + 1];
        float ia8 = 1.0f / alpha[k0 + 8], ia9 = 1.0f / alpha[k0 + 9];
        float2 v00 = *(const float2*)(x0);
        float2 v10 = *(const float2*)(x8);
        float2 v08 = *(const float2*)(x0 + 8);
        float2 v18 = *(const float2*)(x8 + 8);
        uint4 o;
        o.x = h2u(__floats2half2_rn(v00.x * ia0, v00.y * ia1));
        o.y = h2u(__floats2half2_rn(v10.x * ia0, v10.y * ia1));
        o.z = h2u(__floats2half2_rn(v08.x * ia8, v08.y * ia9));
        o.w = h2u(__floats2half2_rn(v18.x * ia8, v18.y * ia9));
        *(uint4*)(g_A + (size_t)j * 4) = o;
    }
}

// ---------------- GEMM: 128x128 CTA, 4 warps (2x2) of 64x64 -------------
__global__ __launch_bounds__(128, 2)
void awq_gemm_kernel(const float* __restrict__ bias, float* __restrict__ out) {
    extern __shared__ char sm[];
    const uint32_t sbase = smem_u32(sm);
    int tid = threadIdx.x, wid = tid >> 5, t = tid & 31;
    int wm = wid & 1, wn = wid >> 1;              // 2 x 2 warp grid
    int mt = blockIdx.x, nt = blockIdx.y;

    const char* gA = (const char*)g_A + (size_t)mt * NKT * A_KT_BYTES;
    const char* gB = (const char*)g_B + (size_t)nt * NKT * B_KT_BYTES;

    const uint32_t cpoff = sbase + (uint32_t)tid * 16;
    auto copy_stage = [&](int kt, uint32_t pbase) {
        const char* srcA = gA + (size_t)kt * A_KT_BYTES + tid * 16;
#pragma unroll
        for (int r = 0; r < 8; r++)               // 16KB A, 2KB/pass
            cp16(cpoff + pbase + r * 2048, srcA + r * 2048);
        const char* srcB = gB + (size_t)kt * B_KT_BYTES + tid * 16;
#pragma unroll
        for (int r = 0; r < 8; r++)               // 16KB B
            cp16(cpoff + pbase + A_KT_BYTES + r * 2048, srcB + r * 2048);
    };

    copy_stage(0, 0); CP_COMMIT();
    copy_stage(1, STAGE_BYTES); CP_COMMIT();

    float4 acc[4][8];
#pragma unroll
    for (int i = 0; i < 4; i++)
#pragma unroll
        for (int jj = 0; jj < 8; jj++) acc[i][jj] = make_float4(0.f, 0.f, 0.f, 0.f);

    // per-thread constant frag offsets within a stage
    const int aoff = wm * 2048 + t * 16;                  // it = wm*4 + il
    const int boff = A_KT_BYTES + wn * 2048 + t * 16;     // jp = wn*4 + pl

    uint4 fa[2][4], fb[2][4];
    auto load_frag = [&](int bi, const char* stage, int s) {
        const char* ab = stage + s * 4096 + aoff;
        const char* bb = stage + s * 4096 + boff;
#pragma unroll
        for (int il = 0; il < 4; il++) fa[bi][il] = *(const uint4*)(ab + il * 512);
#pragma unroll
        for (int pl = 0; pl < 4; pl++) fb[bi][pl] = *(const uint4*)(bb + pl * 512);
    };
    auto do_mma = [&](int bi) {
#pragma unroll
        for (int il = 0; il < 4; il++)
#pragma unroll
            for (int jj = 0; jj < 8; jj++) {
                const uint4& bp = fb[bi][jj >> 1];
                if (jj & 1) mma_f16(acc[il][jj], fa[bi][il], bp.z, bp.w);
                else        mma_f16(acc[il][jj], fa[bi][il], bp.x, bp.y);
            }
    };

    // prologue: stages 0,1 arrived & visible; preload stage0 s0 frags
    CP_WAIT0();
    __syncthreads();
    load_frag(0, sm, 0);

    const char* stages[3] = { sm, sm + STAGE_BYTES, sm + 2 * STAGE_BYTES };
    int p = 0;                                    // slot of stage kt
    for (int kt = 0; kt < NKT; kt++) {
        const char* stage = stages[p];
        int pn = (p + 1 == 3) ? 0 : p + 1;
        int pw = (pn + 1 == 3) ? 0 : pn + 1;      // slot for kt+2
        if (kt + 2 < NKT) copy_stage(kt + 2, (uint32_t)(pw * STAGE_BYTES));
        CP_COMMIT();
#pragma unroll
        for (int s = 0; s < 4; s++) {
            int cur = s & 1;
            if (s < 3) load_frag(cur ^ 1, stage, s + 1);
            else if (kt + 1 < NKT)   // next stage's s0 (arrived & published)
                load_frag(cur ^ 1, stages[pn], 0);
            do_mma(cur);
        }
        CP_WAIT0();          // stage kt+1 (and kt+2) arrived
        __syncthreads();     // publish cross-thread; protect slot reuse
        p = pn;
    }

    // ---- epilogue ----
    int quad = t >> 2, tq = t & 3;
    int row_base = mt * TM + wm * 64;
    int col_base = nt * TN + wn * 64;
#pragma unroll
    for (int il = 0; il < 4; il++) {
        int r0 = row_base + il * 16 + quad;
        float* o0 = out + (size_t)r0 * OUT_F;
        float* o1 = o0 + (size_t)8 * OUT_F;
#pragma unroll
        for (int jj = 0; jj < 8; jj++) {
            int cc = col_base + jj * 8 + tq * 2;
            float2 bv = *(const float2*)(bias + cc);
            float4 v = acc[il][jj];
            *(float2*)(o0 + cc) = make_float2(v.x + bv.x, v.y + bv.y);
            *(float2*)(o1 + cc) = make_float2(v.z + bv.x, v.w + bv.y);
        }
    }
}

// ---------------- launch ----------------
extern "C" void kernel_launch(void* const* d_in, const int* in_sizes, int n_in,
                              void* d_out, int out_size) {
    const float* x     = (const float*)d_in[0];
    const int*   qw    = (const int*)d_in[1];
    const float* sc    = (const float*)d_in[2];
    const float* alpha = (const float*)d_in[3];
    const float* bias  = (const float*)d_in[4];
    float* out = (float*)d_out;

    cudaFuncSetAttribute(awq_gemm_kernel,
                         cudaFuncAttributeMaxDynamicSharedMemorySize, SMEM_BYTES);

    prep_all_kernel<<<WBLOCKS + XBLOCKS, 256>>>(x, alpha, qw, sc);

    dim3 grid(MROWS / TM, OUT_F / TN);            // (32, 86)
    awq_gemm_kernel<<<grid, 128, SMEM_BYTES>>>(bias, out);
}

// round 9
// speedup vs baseline: 1.0323x; 1.0323x over previous
#include <cuda_runtime.h>
#include <cuda_fp16.h>
#include <cstdint>

// ============================================================
// AWQLinear via fp16 mma.sync m16n8k16 (same mantissa as tf32).
// y = (x/alpha) @ W_hat^T + bias, M=4096 N=11008 K=4096.
// R8: 128x128 CTA (4 warps of 64x64), 2 CTAs/SM, 3-stage
// cp.async pipeline with wait_group 1 (one copy always in
// flight). Co-resident CTA covers sync seams. Merged prep.
// ============================================================

#define IN_F   4096
#define OUT_F  11008
#define MROWS  4096
#define NKT    64            // K / 64
#define TM     128
#define TN     128
#define A_KT_BYTES 16384     // 128 rows x 64 k x 2B
#define B_KT_BYTES 16384
#define STAGE_BYTES (A_KT_BYTES + B_KT_BYTES)   // 32KB
#define SMEM_BYTES (3 * STAGE_BYTES)            // 96KB (2 CTAs/SM)

#define XCHUNKS (MROWS * IN_F / 8)              // 2,097,152
#define WCHUNKS (OUT_F * IN_F / 8)              // 5,636,096
#define WBLOCKS (WCHUNKS / 256)                 // 22016
#define XBLOCKS (XCHUNKS / 256)                 // 8192

__device__ __half2 g_A[(size_t)XCHUNKS * 4];    // 32MB
__device__ __half2 g_B[(size_t)WCHUNKS * 4];    // 90MB

// ---------------- helpers ----------------
__device__ __forceinline__ uint32_t smem_u32(const void* p) {
    uint32_t a;
    asm("{ .reg .u64 t; cvta.to.shared.u64 t, %1; cvt.u32.u64 %0, t; }"
        : "=r"(a) : "l"(p));
    return a;
}
__device__ __forceinline__ void cp16(uint32_t dst, const void* src) {
    asm volatile("cp.async.cg.shared.global [%0], [%1], 16;"
                 :: "r"(dst), "l"(src) : "memory");
}
#define CP_COMMIT() asm volatile("cp.async.commit_group;" ::: "memory")
#define CP_WAIT1()  asm volatile("cp.async.wait_group 1;" ::: "memory")

__device__ __forceinline__ void mma_f16(float4& d, const uint4 a,
                                        const uint32_t b0, const uint32_t b1) {
    asm("mma.sync.aligned.m16n8k16.row.col.f32.f16.f16.f32 "
        "{%0,%1,%2,%3}, {%4,%5,%6,%7}, {%8,%9}, {%0,%1,%2,%3};"
        : "+f"(d.x), "+f"(d.y), "+f"(d.z), "+f"(d.w)
        : "r"(a.x), "r"(a.y), "r"(a.z), "r"(a.w), "r"(b0), "r"(b1));
}
__device__ __forceinline__ uint32_t h2u(__half2 h) { return *(uint32_t*)&h; }

// ---------------- merged prep: 1 thread = one 16B fragment chunk --------
__global__ void prep_all_kernel(const float* __restrict__ x,
                                const float* __restrict__ alpha,
                                const int* __restrict__ q,
                                const float* __restrict__ sc) {
    int bid = blockIdx.x;
    if (bid < WBLOCKS) {
        int j = bid * 256 + threadIdx.x;
        int blk = j >> 10, c = j & 1023;
        int th = c & 31, jp = (c >> 5) & 7, s = c >> 8;
        int nb = blk >> 6, kt = blk & 63;
        int o0 = (nb << 7) + (jp << 4) + (th >> 2);
        int k0 = (kt << 6) + (s << 4) + ((th & 3) << 1);
        int sblk = (kt << 1) + (s >> 1);
        const int* q0 = q + ((size_t)o0 << 12) + k0;
        const int* q8 = q0 + (8 << 12);
        float s0 = sc[(o0 << 7) + sblk];
        float s1 = sc[((o0 + 8) << 7) + sblk];
        int2 a0 = *(const int2*)(q0);
        int2 a2 = *(const int2*)(q0 + 8);
        int2 b0 = *(const int2*)(q8);
        int2 b2 = *(const int2*)(q8 + 8);
        uint4 o;
        o.x = h2u(__floats2half2_rn((float)(a0.x - 8) * s0, (float)(a0.y - 8) * s0));
        o.y = h2u(__floats2half2_rn((float)(a2.x - 8) * s0, (float)(a2.y - 8) * s0));
        o.z = h2u(__floats2half2_rn((float)(b0.x - 8) * s1, (float)(b0.y - 8) * s1));
        o.w = h2u(__floats2half2_rn((float)(b2.x - 8) * s1, (float)(b2.y - 8) * s1));
        *(uint4*)(g_B + (size_t)j * 4) = o;
    } else {
        int j = (bid - WBLOCKS) * 256 + threadIdx.x;
        int blk = j >> 10, c = j & 1023;
        int th = c & 31, it = (c >> 5) & 7, s = c >> 8;
        int mb = blk >> 6, kt = blk & 63;
        int row0 = (mb << 7) + (it << 4) + (th >> 2);
        int k0 = (kt << 6) + (s << 4) + ((th & 3) << 1);
        const float* x0 = x + ((size_t)row0 << 12) + k0;
        const float* x8 = x0 + (8 << 12);
        float ia0 = 1.0f / alpha[k0],     ia1 = 1.0f / alpha[k0 + 1];
        float ia8 = 1.0f / alpha[k0 + 8], ia9 = 1.0f / alpha[k0 + 9];
        float2 v00 = *(const float2*)(x0);
        float2 v10 = *(const float2*)(x8);
        float2 v08 = *(const float2*)(x0 + 8);
        float2 v18 = *(const float2*)(x8 + 8);
        uint4 o;
        o.x = h2u(__floats2half2_rn(v00.x * ia0, v00.y * ia1));
        o.y = h2u(__floats2half2_rn(v10.x * ia0, v10.y * ia1));
        o.z = h2u(__floats2half2_rn(v08.x * ia8, v08.y * ia9));
        o.w = h2u(__floats2half2_rn(v18.x * ia8, v18.y * ia9));
        *(uint4*)(g_A + (size_t)j * 4) = o;
    }
}

// ---------------- GEMM: 128x128 CTA, 4 warps (2x2) of 64x64 -------------
__global__ __launch_bounds__(128, 2)
void awq_gemm_kernel(const float* __restrict__ bias, float* __restrict__ out) {
    extern __shared__ char sm[];
    const uint32_t sbase = smem_u32(sm);
    int tid = threadIdx.x, wid = tid >> 5, t = tid & 31;
    int wm = wid & 1, wn = wid >> 1;              // 2 x 2 warp grid
    int mt = blockIdx.x, nt = blockIdx.y;

    const char* gA = (const char*)g_A + (size_t)mt * NKT * A_KT_BYTES;
    const char* gB = (const char*)g_B + (size_t)nt * NKT * B_KT_BYTES;

    const uint32_t cpoff = sbase + (uint32_t)tid * 16;
    auto copy_stage = [&](int kt, uint32_t pbase) {
        const char* srcA = gA + (size_t)kt * A_KT_BYTES + tid * 16;
#pragma unroll
        for (int r = 0; r < 8; r++)               // 16KB A
            cp16(cpoff + pbase + r * 2048, srcA + r * 2048);
        const char* srcB = gB + (size_t)kt * B_KT_BYTES + tid * 16;
#pragma unroll
        for (int r = 0; r < 8; r++)               // 16KB B
            cp16(cpoff + pbase + A_KT_BYTES + r * 2048, srcB + r * 2048);
    };

    copy_stage(0, 0); CP_COMMIT();
    copy_stage(1, STAGE_BYTES); CP_COMMIT();

    float4 acc[4][8];
#pragma unroll
    for (int i = 0; i < 4; i++)
#pragma unroll
        for (int jj = 0; jj < 8; jj++) acc[i][jj] = make_float4(0.f, 0.f, 0.f, 0.f);

    const int aoff = wm * 2048 + t * 16;
    const int boff = A_KT_BYTES + wn * 2048 + t * 16;

    uint4 fa[2][4], fb[2][4];
    auto load_frag = [&](int bi, const char* stage, int s) {
        const char* ab = stage + s * 4096 + aoff;
        const char* bb = stage + s * 4096 + boff;
#pragma unroll
        for (int il = 0; il < 4; il++) fa[bi][il] = *(const uint4*)(ab + il * 512);
#pragma unroll
        for (int pl = 0; pl < 4; pl++) fb[bi][pl] = *(const uint4*)(bb + pl * 512);
    };
    auto do_mma = [&](int bi) {
#pragma unroll
        for (int il = 0; il < 4; il++)
#pragma unroll
            for (int jj = 0; jj < 8; jj++) {
                const uint4& bp = fb[bi][jj >> 1];
                if (jj & 1) mma_f16(acc[il][jj], fa[bi][il], bp.z, bp.w);
                else        mma_f16(acc[il][jj], fa[bi][il], bp.x, bp.y);
            }
    };

    // prologue: wait until stage 0 arrived (<=1 group pending)
    CP_WAIT1();
    __syncthreads();

    const char* stages[3] = { sm, sm + STAGE_BYTES, sm + 2 * STAGE_BYTES };
    int p = 0;
    for (int kt = 0; kt < NKT; kt++) {
        const char* stage = stages[p];
        int pn = (p + 1 == 3) ? 0 : p + 1;
        int pw = (pn + 1 == 3) ? 0 : pn + 1;      // slot for kt+2
        if (kt + 2 < NKT) copy_stage(kt + 2, (uint32_t)(pw * STAGE_BYTES));
        CP_COMMIT();
        load_frag(0, stage, 0);
#pragma unroll
        for (int s = 0; s < 4; s++) {
            int cur = s & 1;
            if (s < 3) load_frag(cur ^ 1, stage, s + 1);
            do_mma(cur);
        }
        CP_WAIT1();          // stage kt+1 arrived; kt+2 may be in flight
        __syncthreads();     // publish cross-thread; protect slot reuse
        p = pn;
    }

    // ---- epilogue ----
    int quad = t >> 2, tq = t & 3;
    int row_base = mt * TM + wm * 64;
    int col_base = nt * TN + wn * 64;
#pragma unroll
    for (int il = 0; il < 4; il++) {
        int r0 = row_base + il * 16 + quad;
        float* o0 = out + (size_t)r0 * OUT_F;
        float* o1 = o0 + (size_t)8 * OUT_F;
#pragma unroll
        for (int jj = 0; jj < 8; jj++) {
            int cc = col_base + jj * 8 + tq * 2;
            float2 bv = *(const float2*)(bias + cc);
            float4 v = acc[il][jj];
            *(float2*)(o0 + cc) = make_float2(v.x + bv.x, v.y + bv.y);
            *(float2*)(o1 + cc) = make_float2(v.z + bv.x, v.w + bv.y);
        }
    }
}

// ---------------- launch ----------------
extern "C" void kernel_launch(void* const* d_in, const int* in_sizes, int n_in,
                              void* d_out, int out_size) {
    const float* x     = (const float*)d_in[0];
    const int*   qw    = (const int*)d_in[1];
    const float* sc    = (const float*)d_in[2];
    const float* alpha = (const float*)d_in[3];
    const float* bias  = (const float*)d_in[4];
    float* out = (float*)d_out;

    cudaFuncSetAttribute(awq_gemm_kernel,
                         cudaFuncAttributeMaxDynamicSharedMemorySize, SMEM_BYTES);

    prep_all_kernel<<<WBLOCKS + XBLOCKS, 256>>>(x, alpha, qw, sc);

    dim3 grid(MROWS / TM, OUT_F / TN);            // (32, 86)
    awq_gemm_kernel<<<grid, 128, SMEM_BYTES>>>(bias, out);
}